// round 13
// baseline (speedup 1.0000x reference)
#include <cuda_runtime.h>
#include <cuda_bf16.h>
#include <cuda_fp8.h>
#include <cstdint>

// ---------------------------------------------------------------------------
// TopK SAE: B=4096, D_IN=1024, N_LAT=16384, K=32
// Outputs: [recon f32 | acts f32 | idx f32]
//
// Bit-exactness model (validated R6-R11, rel_err == 0.0):
//   enc pre_act = ((p0 + p1) + bias), p0 = serial FMA k=0..511, p1 = 512..1023
//   decode      = latent panels of 512 (l>>9), serial ascending-l FMA within
//                 panel, partials added ascending, + dec_b last
// R12: screening GEMM switched bf16->FP8 e4m3 (m16n8k32, half the mma
// instructions at the same legacy-tensor issue rate); candidate set widened
// to 96 (6.5-sigma membership margin vs fp8 noise); refine recomputes all 96
// scheme-exactly, so final outputs remain bit-exact.
// ---------------------------------------------------------------------------

#define B_ROWS   4096
#define D_IN     1024
#define N_LAT    16384
#define KSEL     32
#define NCAND    96

// ------------------------- device scratch ----------------------------------
__device__ __nv_bfloat16 g_preb[(size_t)B_ROWS * N_LAT];   // 128 MB
__device__ uint8_t g_xq [(size_t)B_ROWS * D_IN];           // 4 MB  (fp8 x)
__device__ uint8_t g_wq [(size_t)N_LAT * D_IN];            // 16 MB (fp8 w*64)
__device__ float g_wt  [(size_t)N_LAT * D_IN];             // 64 MB (dec_w^T)
__device__ float g_val [B_ROWS * KSEL];
__device__ int   g_sidx[B_ROWS * KSEL];
__device__ int   g_cidx[B_ROWS * NCAND];

// ------------------------- mma / ldmatrix / cp.async helpers ----------------
__device__ __forceinline__ void ldsm4(uint32_t& r0, uint32_t& r1,
                                      uint32_t& r2, uint32_t& r3,
                                      uint32_t addr) {
    asm volatile("ldmatrix.sync.aligned.m8n8.x4.shared.b16 {%0,%1,%2,%3}, [%4];"
                 : "=r"(r0), "=r"(r1), "=r"(r2), "=r"(r3) : "r"(addr));
}
// FP8 E4M3 mma, K=32. Fragment bytes are identical to the bf16 k16 layout
// (one 16-bit unit == two consecutive fp8 along k), so ldmatrix.b16 loads
// the correct fragments.
__device__ __forceinline__ void mma_fp8(float* c, const uint32_t* a,
                                        const uint32_t* b) {
    asm volatile(
        "mma.sync.aligned.m16n8k32.row.col.f32.e4m3.e4m3.f32 "
        "{%0,%1,%2,%3}, {%4,%5,%6,%7}, {%8,%9}, {%0,%1,%2,%3};"
        : "+f"(c[0]), "+f"(c[1]), "+f"(c[2]), "+f"(c[3])
        : "r"(a[0]), "r"(a[1]), "r"(a[2]), "r"(a[3]), "r"(b[0]), "r"(b[1]));
}
__device__ __forceinline__ void cp16(uint32_t dst, const void* src) {
    asm volatile("cp.async.cg.shared.global [%0], [%1], 16;"
                 :: "r"(dst), "l"(src));
}
#define CP_COMMIT()  asm volatile("cp.async.commit_group;" ::: "memory")
#define CP_WAIT(n)   asm volatile("cp.async.wait_group %0;" :: "n"(n) : "memory")

// ------------------------- fp32 -> fp8 conversion ---------------------------
__global__ void __launch_bounds__(256) cvt_fp8(const float* __restrict__ src,
                                               uint8_t* __restrict__ dst,
                                               float scale, int n4) {
    int i = blockIdx.x * 256 + threadIdx.x;
    if (i < n4) {
        float4 v = ((const float4*)src)[i];
        uint32_t b0 = __nv_cvt_float_to_fp8(v.x * scale, __NV_SATFINITE, __NV_E4M3);
        uint32_t b1 = __nv_cvt_float_to_fp8(v.y * scale, __NV_SATFINITE, __NV_E4M3);
        uint32_t b2 = __nv_cvt_float_to_fp8(v.z * scale, __NV_SATFINITE, __NV_E4M3);
        uint32_t b3 = __nv_cvt_float_to_fp8(v.w * scale, __NV_SATFINITE, __NV_E4M3);
        ((uint32_t*)dst)[i] = b0 | (b1 << 8) | (b2 << 16) | (b3 << 24);
    }
}

// ------------------------- zero acts ----------------------------------------
__global__ void __launch_bounds__(256) zero_kernel(float4* __restrict__ p,
                                                   int n4) {
    int stride = gridDim.x * 256;
    float4 z = make_float4(0.f, 0.f, 0.f, 0.f);
    for (int i = blockIdx.x * 256 + threadIdx.x; i < n4; i += stride)
        p[i] = z;
}

// ------------------------- FP8 mma.sync encoder GEMM ------------------------
// P[4096,16384](bf16) = (Xq * Wq^T) / 64 + bias, fp8 e4m3 inputs.
// Tile 128(M) x 256(N) x 64(K-fp8), 512 threads (16 warps, 2m x 8n),
// warp tile 64x32 (4x4 m16n8k32), cp.async 2-stage pipeline.
// Smem rows: 64 data bytes + 16 pad = 80B (same bank pattern as R9-R11).
constexpr int LDTB = 80;                      // smem row pitch (bytes)
constexpr int AS_BYTES = 128 * LDTB;          // 10240
constexpr int BS_BYTES = 256 * LDTB;          // 20480
constexpr int GSMEM = 2 * AS_BYTES + 2 * BS_BYTES;   // 61440

__global__ void __launch_bounds__(512) enc_gemm_fp8(
    const uint8_t* __restrict__ Xq,
    const uint8_t* __restrict__ Wq,
    const float* __restrict__ bias,
    __nv_bfloat16* __restrict__ P) {
    extern __shared__ char smem[];
    char* As0 = smem;                      // [2][128][80B]
    char* Bs0 = smem + 2 * AS_BYTES;       // [2][256][80B]

    const int tid    = threadIdx.x;
    const int wid    = tid >> 5;
    const int lane   = tid & 31;
    const int bm     = blockIdx.y * 128;
    const int bn     = blockIdx.x * 256;
    const int warp_m = (wid >> 3) * 64;     // 2 m-groups
    const int warp_n = (wid & 7) * 32;      // 8 n-groups

    float c[4][4][4];
#pragma unroll
    for (int i = 0; i < 4; i++)
#pragma unroll
        for (int j = 0; j < 4; j++)
#pragma unroll
            for (int q = 0; q < 4; q++) c[i][j][q] = 0.f;

    const int arow = tid >> 2;        // 0..127
    const int aseg = tid & 3;         // 16B segment within 64B row-chunk

    auto load_chunk = [&](int kt, int buf) {   // kt in bytes (fp8 elems)
        {
            uint32_t dst = (uint32_t)__cvta_generic_to_shared(
                As0 + buf * AS_BYTES + arow * LDTB + aseg * 16);
            cp16(dst, Xq + (size_t)(bm + arow) * D_IN + kt + aseg * 16);
        }
#pragma unroll
        for (int r = 0; r < 2; r++) {
            int brow = arow + r * 128;
            uint32_t dst = (uint32_t)__cvta_generic_to_shared(
                Bs0 + buf * BS_BYTES + brow * LDTB + aseg * 16);
            cp16(dst, Wq + (size_t)(bn + brow) * D_IN + kt + aseg * 16);
        }
        CP_COMMIT();
    };

    load_chunk(0, 0);

    const int NT = D_IN / 64;   // 16 chunks of 64 fp8
    for (int t = 0; t < NT; t++) {
        const int buf = t & 1;
        if (t < NT - 1) load_chunk((t + 1) * 64, buf ^ 1);
        if (t < NT - 1) { CP_WAIT(1); } else { CP_WAIT(0); }
        __syncthreads();

        const char* Ab = As0 + buf * AS_BYTES;
        const char* Bb = Bs0 + buf * BS_BYTES;
#pragma unroll
        for (int s = 0; s < 2; s++) {              // two k32 halves (32B each)
            uint32_t af[4][4];
#pragma unroll
            for (int mt = 0; mt < 4; mt++) {
                uint32_t addr = (uint32_t)__cvta_generic_to_shared(
                    Ab + (warp_m + mt * 16 + (lane & 15)) * LDTB +
                    s * 32 + (lane >> 4) * 16);
                ldsm4(af[mt][0], af[mt][1], af[mt][2], af[mt][3], addr);
            }
            uint32_t bf[4][2];
#pragma unroll
            for (int p = 0; p < 2; p++) {
                uint32_t r0, r1, r2, r3;
                uint32_t addr = (uint32_t)__cvta_generic_to_shared(
                    Bb + (warp_n + p * 16 + (lane & 7) + ((lane >> 4) << 3)) * LDTB +
                    s * 32 + (((lane >> 3) & 1) * 16));
                ldsm4(r0, r1, r2, r3, addr);
                bf[2 * p][0] = r0; bf[2 * p][1] = r1;
                bf[2 * p + 1][0] = r2; bf[2 * p + 1][1] = r3;
            }
#pragma unroll
            for (int mt = 0; mt < 4; mt++)
#pragma unroll
                for (int nt = 0; nt < 4; nt++)
                    mma_fp8(c[mt][nt], af[mt], bf[nt]);
        }
        __syncthreads();
    }

    // epilogue: /64 (w was pre-scaled x64), +bias, convert to bf16, store
    const float inv = 0.015625f;
#pragma unroll
    for (int nt = 0; nt < 4; nt++) {
        int col = bn + warp_n + nt * 8 + (lane & 3) * 2;
        float b0 = bias[col], b1 = bias[col + 1];
#pragma unroll
        for (int mt = 0; mt < 4; mt++) {
            int row0 = bm + warp_m + mt * 16 + (lane >> 2);
            __nv_bfloat162 v0 = __floats2bfloat162_rn(
                fmaf(c[mt][nt][0], inv, b0), fmaf(c[mt][nt][1], inv, b1));
            __nv_bfloat162 v1 = __floats2bfloat162_rn(
                fmaf(c[mt][nt][2], inv, b0), fmaf(c[mt][nt][3], inv, b1));
            *(__nv_bfloat162*)&P[(size_t)row0 * N_LAT + col] = v0;
            *(__nv_bfloat162*)&P[(size_t)(row0 + 8) * N_LAT + col] = v1;
        }
    }
}

// ------------------------- top-NCAND selection -------------------------------
// Two-pass radix-select with per-warp privatized packed histograms (R11).
__device__ __forceinline__ unsigned key16(unsigned short h) {
    return h ^ ((h & 0x8000u) ? 0xFFFFu : 0x8000u);
}

__global__ void __launch_bounds__(256) topk_kernel(
    const __nv_bfloat16* __restrict__ P) {
    __shared__ uint32_t hist[8][1024];   // 32 KB: warp-private packed bins
    __shared__ unsigned csum[256];       // chunk sums (8 bins per chunk)
    __shared__ unsigned cu[1024];
    __shared__ int      cix[1024];
    __shared__ int      thr_bin, cnt_gt;
    __shared__ int      n_sel, n_cand;

    const int tid = threadIdx.x;
    const int wid = tid >> 5;
    const int b   = blockIdx.x;
    const uint4* row8 = (const uint4*)(P + (size_t)b * N_LAT);
    int* out = g_cidx + (size_t)b * NCAND;

    for (int i = tid; i < 8 * 1024; i += 256) ((uint32_t*)hist)[i] = 0;
    if (tid == 0) { n_sel = 0; n_cand = 0; }
    __syncthreads();

    // pass 1: per-warp packed histogram of key16 >> 5
    for (int i = tid; i < N_LAT / 8; i += 256) {
        uint4 v = row8[i];
        unsigned w[4] = {v.x, v.y, v.z, v.w};
#pragma unroll
        for (int q = 0; q < 4; q++) {
            unsigned b0 = key16((unsigned short)(w[q] & 0xFFFFu)) >> 5;
            unsigned b1 = key16((unsigned short)(w[q] >> 16)) >> 5;
            atomicAdd(&hist[wid][b0 >> 1], 1u << ((b0 & 1) * 16));
            atomicAdd(&hist[wid][b1 >> 1], 1u << ((b1 & 1) * 16));
        }
    }
    __syncthreads();

    // merge: chunk t = bins 8t..8t+7 = words 4t..4t+3 across 8 warp banks
    {
        unsigned S = 0;
#pragma unroll
        for (int w = 0; w < 8; w++)
#pragma unroll
            for (int k = 0; k < 4; k++)
                S += hist[w][tid * 4 + k];
        csum[tid] = (S & 0xFFFFu) + (S >> 16);
    }
    __syncthreads();

    if (tid == 0) {
        unsigned acc = 0;
        int cchunk = 255;
        for (; cchunk >= 0; cchunk--) {
            if (acc + csum[cchunk] >= NCAND) break;
            acc += csum[cchunk];
        }
        int bin = cchunk * 8 + 7;
        for (; bin >= cchunk * 8; bin--) {
            unsigned bc = 0;
#pragma unroll
            for (int w = 0; w < 8; w++)
                bc += (hist[w][bin >> 1] >> ((bin & 1) * 16)) & 0xFFFFu;
            if (acc + bc >= NCAND) break;
            acc += bc;
        }
        thr_bin = bin;
        cnt_gt  = (int)acc;     // strictly above threshold bin (< NCAND)
    }
    __syncthreads();
    const int tb = thr_bin;
    const int hi = cnt_gt;

    // pass 2 (vectorized): definite winners + threshold-bin candidates.
    for (int i = tid; i < N_LAT / 8; i += 256) {
        uint4 v = row8[i];
        unsigned w[4] = {v.x, v.y, v.z, v.w};
#pragma unroll
        for (int q = 0; q < 4; q++) {
#pragma unroll
            for (int h = 0; h < 2; h++) {
                unsigned u = key16((unsigned short)((w[q] >> (16 * h)) & 0xFFFFu));
                int bin = (int)(u >> 5);
                if (bin >= tb) {
                    int idx = i * 8 + q * 2 + h;
                    if (bin > tb) {
                        int p = atomicAdd(&n_sel, 1);
                        out[p] = idx;
                    } else {
                        int p = atomicAdd(&n_cand, 1);
                        if (p < 1024) { cu[p] = u; cix[p] = idx; }
                    }
                }
            }
        }
    }
    __syncthreads();

    const int need = NCAND - hi;
    const int C = min(n_cand, 1024);
    for (int i = tid; i < C; i += 256) {
        unsigned ui = cu[i];
        int ii = cix[i];
        int rank = 0;
        for (int j = 0; j < C; j++) {
            unsigned uj = cu[j];
            rank += (uj > ui) || (uj == ui && cix[j] < ii);
        }
        if (rank < need) out[hi + rank] = ii;
    }
}

// ------------------------- scheme-exact refine (96 candidates) ---------------
__global__ void __launch_bounds__(256) refine_kernel(
    const float* __restrict__ X,
    const float* __restrict__ W,
    const float* __restrict__ bias,
    float* __restrict__ o_acts,
    float* __restrict__ o_idx) {
    __shared__ float xs[D_IN];
    __shared__ float vv[NCAND];
    __shared__ int   ci[NCAND];
    __shared__ int   si[KSEL];
    __shared__ float sv[KSEL];

    const int b   = blockIdx.x;
    const int tid = threadIdx.x;

    for (int i = tid; i < D_IN / 4; i += 256)
        ((float4*)xs)[i] = ((const float4*)(X + (size_t)b * D_IN))[i];
    if (tid < NCAND) ci[tid] = g_cidx[(size_t)b * NCAND + tid];
    __syncthreads();

    if (tid < 2 * NCAND) {      // 192 threads: one 512-elem chain each
        const int cand = tid >> 1;
        const int half = tid & 1;
        const int l    = ci[cand];
        const float4* wr4 = (const float4*)(W + (size_t)l * D_IN + half * 512);
        const float4* xs4 = (const float4*)(xs + half * 512);
        float p = 0.f;
#pragma unroll 8
        for (int i = 0; i < 128; i++) {
            float4 w = wr4[i];
            float4 x = xs4[i];
            p = fmaf(x.x, w.x, p);
            p = fmaf(x.y, w.y, p);
            p = fmaf(x.z, w.z, p);
            p = fmaf(x.w, w.w, p);
        }
        float other = __shfl_xor_sync(0xFFFFFFFFu, p, 1);
        if (half == 0)
            vv[cand] = (p + other) + bias[l];   // ((p0+p1)+bias)
    }
    __syncthreads();

    if (tid < NCAND) {
        float vi = vv[tid];
        int   ii = ci[tid];
        int rank = 0;
#pragma unroll
        for (int j = 0; j < NCAND; j++) {
            float vj = vv[j];
            rank += (vj > vi) || (vj == vi && ci[j] < ii);
        }
        if (rank < KSEL) { si[rank] = ii; sv[rank] = vi; }
    }
    __syncthreads();

    if (tid < KSEL) {
        g_sidx[b * KSEL + tid] = si[tid];
        g_val [b * KSEL + tid] = fmaxf(sv[tid], 0.0f);
        if (o_idx) o_idx[(size_t)b * KSEL + tid] = (float)si[tid];
        if (o_acts)
            o_acts[(size_t)b * N_LAT + si[tid]] = fmaxf(sv[tid], 0.0f);
    }
}

// ------------------------- dec_w transpose ----------------------------------
__global__ void transp_kernel(const float* __restrict__ W, float* __restrict__ WT) {
    __shared__ float t[32][33];
    int l0 = blockIdx.x * 32;
    int d0 = blockIdx.y * 32;
    int txx = threadIdx.x, tyy = threadIdx.y;
#pragma unroll
    for (int j = 0; j < 32; j += 8)
        t[tyy + j][txx] = W[(size_t)(d0 + tyy + j) * N_LAT + l0 + txx];
    __syncthreads();
#pragma unroll
    for (int j = 0; j < 32; j += 8)
        WT[(size_t)(l0 + tyy + j) * D_IN + d0 + txx] = t[txx][tyy + j];
}

// ------------------------- sparse decode (512-latent panels) -----------------
__global__ void __launch_bounds__(256) decode_kernel(
    const float* __restrict__ WT,
    const float* __restrict__ dec_b,
    float* __restrict__ recon) {
    const int b   = blockIdx.x;
    const int tid = threadIdx.x;
    __shared__ float sv[KSEL];
    __shared__ int   sidx[KSEL];
    __shared__ float sv_s[KSEL];
    __shared__ int   sidx_s[KSEL];

    if (tid < KSEL) {
        sv[tid]   = g_val [b * KSEL + tid];
        sidx[tid] = g_sidx[b * KSEL + tid];
    }
    __syncthreads();
    if (tid < KSEL) {
        int ii = sidx[tid];
        int rank = 0;
#pragma unroll
        for (int j = 0; j < KSEL; j++) rank += (sidx[j] < ii);
        sidx_s[rank] = ii;
        sv_s[rank]   = sv[tid];
    }
    __syncthreads();

    const int d = tid * 4;
    float4 tot  = make_float4(0.f, 0.f, 0.f, 0.f);
    float4 pacc = make_float4(0.f, 0.f, 0.f, 0.f);
    int curPan = sidx_s[0] >> 9;
#pragma unroll
    for (int j = 0; j < KSEL; j++) {
        int   l = sidx_s[j];
        float v = sv_s[j];
        int pan = l >> 9;
        if (pan != curPan) {
            tot.x += pacc.x; tot.y += pacc.y; tot.z += pacc.z; tot.w += pacc.w;
            pacc = make_float4(0.f, 0.f, 0.f, 0.f);
            curPan = pan;
        }
        const float4 w = *(const float4*)&WT[(size_t)l * D_IN + d];
        pacc.x = fmaf(v, w.x, pacc.x);
        pacc.y = fmaf(v, w.y, pacc.y);
        pacc.z = fmaf(v, w.z, pacc.z);
        pacc.w = fmaf(v, w.w, pacc.w);
    }
    tot.x += pacc.x; tot.y += pacc.y; tot.z += pacc.z; tot.w += pacc.w;

    const float4 bb = *(const float4*)&dec_b[d];
    tot.x += bb.x; tot.y += bb.y; tot.z += bb.z; tot.w += bb.w;
    *(float4*)&recon[(size_t)b * D_IN + d] = tot;
}

// ------------------------- launch -------------------------------------------
extern "C" void kernel_launch(void* const* d_in, const int* in_sizes, int n_in,
                              void* d_out, int out_size) {
    const float* x     = (const float*)d_in[0];
    const float* enc_w = (const float*)d_in[1];
    const float* enc_b = (const float*)d_in[2];
    const float* dec_w = (const float*)d_in[3];
    const float* dec_b = (const float*)d_in[4];

    const size_t R = (size_t)B_ROWS * D_IN;
    const size_t A = (size_t)B_ROWS * N_LAT;
    const size_t I = (size_t)B_ROWS * KSEL;
    const size_t os = (size_t)out_size;

    float* out = (float*)d_out;
    float* o_recon = nullptr;
    float* o_acts  = nullptr;
    float* o_idx   = nullptr;
    if (os == R + A + I)      { o_recon = out; o_acts = out + R; o_idx = out + R + A; }
    else if (os == R + A)     { o_recon = out; o_acts = out + R; }
    else if (os == R + I)     { o_recon = out; o_idx  = out + R; }
    else if (os == A + I)     { o_acts  = out; o_idx  = out + A; }
    else if (os == R)         { o_recon = out; }
    else if (os == A)         { o_acts  = out; }
    else {
        o_recon = out;
        if (os >= R + A) o_acts = out + R;
        if (os >= R + A + I) o_idx = out + R + A;
    }

    uint8_t *xq, *wq;
    __nv_bfloat16* preb;
    float* wt;
    cudaGetSymbolAddress((void**)&preb, g_preb);
    cudaGetSymbolAddress((void**)&xq,   g_xq);
    cudaGetSymbolAddress((void**)&wq,   g_wq);
    cudaGetSymbolAddress((void**)&wt,   g_wt);

    // 1. convert x (scale 1) and enc_w (scale 64, exact power of 2) to fp8
    cvt_fp8<<<(int)(R / 4 + 255) / 256, 256>>>(x, xq, 1.0f, (int)(R / 4));
    cvt_fp8<<<(int)(N_LAT * (size_t)D_IN / 4 + 255) / 256, 256>>>(
        enc_w, wq, 64.0f, (int)(N_LAT * (size_t)D_IN / 4));

    // 2. FP8 mma.sync encoder GEMM (membership only)
    cudaFuncSetAttribute(enc_gemm_fp8,
                         cudaFuncAttributeMaxDynamicSharedMemorySize, GSMEM);
    dim3 ggrid(N_LAT / 256, B_ROWS / 128);   // (64, 32)
    enc_gemm_fp8<<<ggrid, 512, GSMEM>>>(xq, wq, enc_b, preb);

    // 3. transpose dec_w
    dim3 tgrid(N_LAT / 32, D_IN / 32);
    transp_kernel<<<tgrid, dim3(32, 8)>>>(dec_w, wt);

    // 4. zero acts
    if (o_acts)
        zero_kernel<<<16384, 256>>>((float4*)o_acts, (int)(A / 4));

    // 5. top-NCAND candidate selection
    topk_kernel<<<B_ROWS, 256>>>(preb);

    // 6. scheme-exact refine: ordering, acts scatter, idx
    refine_kernel<<<B_ROWS, 256>>>(x, enc_w, enc_b, o_acts, o_idx);

    // 7. sparse decode (512-latent panels)
    if (o_recon)
        decode_kernel<<<B_ROWS, 256>>>(wt, dec_b, o_recon);
}

// round 14
// speedup vs baseline: 1.2143x; 1.2143x over previous
#include <cuda_runtime.h>
#include <cuda_bf16.h>
#include <cstdint>

// ---------------------------------------------------------------------------
// TopK SAE: B=4096, D_IN=1024, N_LAT=16384, K=32
// Outputs: [recon f32 | acts f32 | idx f32]
//
// Bit-exactness model (validated R6-R12, rel_err == 0.0):
//   enc pre_act = ((p0 + p1) + bias), p0 = serial FMA k=0..511, p1 = 512..1023
//   decode      = latent panels of 512 (l>>9), serial ascending-l FMA within
//                 panel, partials added ascending, + dec_b last
// Speed: bf16 mma.sync GEMM (membership-only) selects top-48 candidates;
// refine recomputes them scheme-exactly.
// R13: revert to R9 pipeline (fp8 regressed — legacy tensor path is MAC-rate
// bound, not instruction bound); acts-zeroing folded into GEMM epilogue
// (hidden behind tensor work); transp moved before GEMM so the ncu capture
// slot lands on the GEMM for attribution.
// ---------------------------------------------------------------------------

#define B_ROWS   4096
#define D_IN     1024
#define N_LAT    16384
#define KSEL     32
#define NCAND    48

// ------------------------- device scratch ----------------------------------
__device__ __nv_bfloat16 g_preb[(size_t)B_ROWS * N_LAT];   // 128 MB
__device__ __nv_bfloat16 g_xb [(size_t)B_ROWS * D_IN];     // 8 MB
__device__ __nv_bfloat16 g_wb [(size_t)N_LAT * D_IN];      // 32 MB
__device__ float g_wt  [(size_t)N_LAT * D_IN];             // 64 MB (dec_w^T)
__device__ float g_val [B_ROWS * KSEL];
__device__ int   g_sidx[B_ROWS * KSEL];
__device__ int   g_cidx[B_ROWS * NCAND];

// ------------------------- mma / ldmatrix / cp.async helpers ----------------
__device__ __forceinline__ void ldsm4(uint32_t& r0, uint32_t& r1,
                                      uint32_t& r2, uint32_t& r3,
                                      uint32_t addr) {
    asm volatile("ldmatrix.sync.aligned.m8n8.x4.shared.b16 {%0,%1,%2,%3}, [%4];"
                 : "=r"(r0), "=r"(r1), "=r"(r2), "=r"(r3) : "r"(addr));
}
__device__ __forceinline__ void mma_bf16(float* c, const uint32_t* a,
                                         const uint32_t* b) {
    asm volatile(
        "mma.sync.aligned.m16n8k16.row.col.f32.bf16.bf16.f32 "
        "{%0,%1,%2,%3}, {%4,%5,%6,%7}, {%8,%9}, {%0,%1,%2,%3};"
        : "+f"(c[0]), "+f"(c[1]), "+f"(c[2]), "+f"(c[3])
        : "r"(a[0]), "r"(a[1]), "r"(a[2]), "r"(a[3]), "r"(b[0]), "r"(b[1]));
}
__device__ __forceinline__ void cp16(uint32_t dst, const void* src) {
    asm volatile("cp.async.cg.shared.global [%0], [%1], 16;"
                 :: "r"(dst), "l"(src));
}
#define CP_COMMIT()  asm volatile("cp.async.commit_group;" ::: "memory")
#define CP_WAIT(n)   asm volatile("cp.async.wait_group %0;" :: "n"(n) : "memory")

// ------------------------- fp32 -> bf16 conversion --------------------------
__global__ void __launch_bounds__(256) cvt_bf16(const float* __restrict__ src,
                                                __nv_bfloat16* __restrict__ dst,
                                                int n4) {
    int i = blockIdx.x * 256 + threadIdx.x;
    if (i < n4) {
        float4 v = ((const float4*)src)[i];
        __nv_bfloat162 lo = __floats2bfloat162_rn(v.x, v.y);
        __nv_bfloat162 hi = __floats2bfloat162_rn(v.z, v.w);
        uint2 pk;
        pk.x = *(uint32_t*)&lo;
        pk.y = *(uint32_t*)&hi;
        ((uint2*)dst)[i] = pk;
    }
}

// ------------------------- bf16 mma.sync encoder GEMM -----------------------
// P[4096,16384](bf16) = Xb * Wb^T + bias.  Also zeroes this CTA's 128x256
// region of acts (hidden behind tensor work; scatter comes later in refine).
// Tile 128(M) x 256(N) x 32(K), 512 threads (16 warps, 2m x 8n), warp tile
// 64x32 (4x4 m16n8k16), cp.async 2-stage pipeline, dynamic smem.
constexpr int LDT = 40;                       // padded smem row (bf16 elems)
constexpr int AS_BYTES = 128 * LDT * 2;       // 10240
constexpr int BS_BYTES = 256 * LDT * 2;       // 20480
constexpr int GSMEM = 2 * AS_BYTES + 2 * BS_BYTES;   // 61440

__global__ void __launch_bounds__(512) enc_gemm_bf16(
    const __nv_bfloat16* __restrict__ Xb,
    const __nv_bfloat16* __restrict__ Wb,
    const float* __restrict__ bias,
    __nv_bfloat16* __restrict__ P,
    float* __restrict__ acts) {
    extern __shared__ char smem[];
    __nv_bfloat16* As0 = (__nv_bfloat16*)smem;                       // [2][128][LDT]
    __nv_bfloat16* Bs0 = (__nv_bfloat16*)(smem + 2 * AS_BYTES);      // [2][256][LDT]

    const int tid    = threadIdx.x;
    const int wid    = tid >> 5;
    const int lane   = tid & 31;
    const int bm     = blockIdx.y * 128;
    const int bn     = blockIdx.x * 256;
    const int warp_m = (wid >> 3) * 64;     // 2 m-groups
    const int warp_n = (wid & 7) * 32;      // 8 n-groups

    float c[4][4][4];
#pragma unroll
    for (int i = 0; i < 4; i++)
#pragma unroll
        for (int j = 0; j < 4; j++)
#pragma unroll
            for (int q = 0; q < 4; q++) c[i][j][q] = 0.f;

    const int arow = tid >> 2;        // 0..127
    const int aseg = tid & 3;         // 16B segment within 64B row

    auto load_chunk = [&](int kt, int buf) {
        {
            uint32_t dst = (uint32_t)__cvta_generic_to_shared(
                As0 + buf * (AS_BYTES / 2) + arow * LDT + aseg * 8);
            cp16(dst, &Xb[(size_t)(bm + arow) * D_IN + kt + aseg * 8]);
        }
#pragma unroll
        for (int r = 0; r < 2; r++) {
            int brow = arow + r * 128;
            uint32_t dst = (uint32_t)__cvta_generic_to_shared(
                Bs0 + buf * (BS_BYTES / 2) + brow * LDT + aseg * 8);
            cp16(dst, &Wb[(size_t)(bn + brow) * D_IN + kt + aseg * 8]);
        }
        CP_COMMIT();
    };

    load_chunk(0, 0);

    // acts zeroing for this CTA's 128x256 region (overlaps with pipeline)
    if (acts) {
        const float4 z = make_float4(0.f, 0.f, 0.f, 0.f);
#pragma unroll
        for (int i = 0; i < 16; i++) {
            int idx = i * 512 + tid;          // 8192 float4 total
            int r   = idx >> 6;               // 0..127
            int c4  = idx & 63;               // 0..63
            *(float4*)&acts[(size_t)(bm + r) * N_LAT + bn + c4 * 4] = z;
        }
    }

    const int NT = D_IN / 32;   // 32
    for (int t = 0; t < NT; t++) {
        const int buf = t & 1;
        if (t < NT - 1) load_chunk((t + 1) * 32, buf ^ 1);
        if (t < NT - 1) { CP_WAIT(1); } else { CP_WAIT(0); }
        __syncthreads();

        const __nv_bfloat16* Ab = As0 + buf * (AS_BYTES / 2);
        const __nv_bfloat16* Bb = Bs0 + buf * (BS_BYTES / 2);
#pragma unroll
        for (int s = 0; s < 2; s++) {              // two k16 halves
            uint32_t af[4][4];
#pragma unroll
            for (int mt = 0; mt < 4; mt++) {
                uint32_t addr = (uint32_t)__cvta_generic_to_shared(
                    Ab + (warp_m + mt * 16 + (lane & 15)) * LDT +
                    s * 16 + (lane >> 4) * 8);
                ldsm4(af[mt][0], af[mt][1], af[mt][2], af[mt][3], addr);
            }
            uint32_t bf[4][2];
#pragma unroll
            for (int p = 0; p < 2; p++) {
                uint32_t r0, r1, r2, r3;
                uint32_t addr = (uint32_t)__cvta_generic_to_shared(
                    Bb + (warp_n + p * 16 + (lane & 7) + ((lane >> 4) << 3)) * LDT +
                    s * 16 + (((lane >> 3) & 1) * 8));
                ldsm4(r0, r1, r2, r3, addr);
                bf[2 * p][0] = r0; bf[2 * p][1] = r1;
                bf[2 * p + 1][0] = r2; bf[2 * p + 1][1] = r3;
            }
#pragma unroll
            for (int mt = 0; mt < 4; mt++)
#pragma unroll
                for (int nt = 0; nt < 4; nt++)
                    mma_bf16(c[mt][nt], af[mt], bf[nt]);
        }
        __syncthreads();
    }

    // epilogue: +bias, convert to bf16, store
#pragma unroll
    for (int nt = 0; nt < 4; nt++) {
        int col = bn + warp_n + nt * 8 + (lane & 3) * 2;
        float b0 = bias[col], b1 = bias[col + 1];
#pragma unroll
        for (int mt = 0; mt < 4; mt++) {
            int row0 = bm + warp_m + mt * 16 + (lane >> 2);
            __nv_bfloat162 v0 =
                __floats2bfloat162_rn(c[mt][nt][0] + b0, c[mt][nt][1] + b1);
            __nv_bfloat162 v1 =
                __floats2bfloat162_rn(c[mt][nt][2] + b0, c[mt][nt][3] + b1);
            *(__nv_bfloat162*)&P[(size_t)row0 * N_LAT + col] = v0;
            *(__nv_bfloat162*)&P[(size_t)(row0 + 8) * N_LAT + col] = v1;
        }
    }
}

// ------------------------- top-NCAND selection (bf16 pre) --------------------
__device__ __forceinline__ unsigned key16(unsigned short h) {
    return h ^ ((h & 0x8000u) ? 0xFFFFu : 0x8000u);
}

__global__ void __launch_bounds__(256) topk_kernel(
    const __nv_bfloat16* __restrict__ P) {
    __shared__ unsigned hist[4096];
    __shared__ int      cand_i[4096];
    __shared__ unsigned csum[256];
    __shared__ int      thr_bin, cnt_gt;
    __shared__ int      n_sel, n_cand;

    const int tid = threadIdx.x;
    const int b   = blockIdx.x;
    const unsigned short* row = (const unsigned short*)(P + (size_t)b * N_LAT);
    int* out = g_cidx + (size_t)b * NCAND;

    for (int i = tid; i < 4096; i += 256) hist[i] = 0;
    if (tid == 0) { n_sel = 0; n_cand = 0; }
    __syncthreads();

    const uint4* row8 = (const uint4*)row;
    for (int i = tid; i < N_LAT / 8; i += 256) {
        uint4 v = row8[i];
        unsigned w[4] = {v.x, v.y, v.z, v.w};
#pragma unroll
        for (int q = 0; q < 4; q++) {
            atomicAdd(&hist[key16((unsigned short)(w[q] & 0xFFFF)) >> 4], 1u);
            atomicAdd(&hist[key16((unsigned short)(w[q] >> 16)) >> 4], 1u);
        }
    }
    __syncthreads();

    {
        unsigned s = 0;
#pragma unroll 4
        for (int j = 0; j < 16; j++) s += hist[tid * 16 + j];
        csum[tid] = s;
    }
    __syncthreads();

    if (tid == 0) {
        unsigned acc = 0;
        int cchunk = 255;
        for (; cchunk >= 0; cchunk--) {
            if (acc + csum[cchunk] >= NCAND) break;
            acc += csum[cchunk];
        }
        int bin = cchunk * 16 + 15;
        for (; bin >= cchunk * 16; bin--) {
            if (acc + hist[bin] >= NCAND) break;
            acc += hist[bin];
        }
        thr_bin = bin;
        cnt_gt  = (int)acc;
    }
    __syncthreads();
    const int tb = thr_bin;
    const int hi = cnt_gt;
    __syncthreads();

    // pass 2 (vectorized): definite winners + threshold-bin candidates.
    // out[] ordering irrelevant: refine re-ranks all NCAND exactly.
    unsigned* cand_u = hist;
    for (int i = tid; i < N_LAT / 8; i += 256) {
        uint4 v = row8[i];
        unsigned w[4] = {v.x, v.y, v.z, v.w};
#pragma unroll
        for (int q = 0; q < 4; q++) {
#pragma unroll
            for (int h = 0; h < 2; h++) {
                unsigned u = key16((unsigned short)((w[q] >> (16 * h)) & 0xFFFF));
                int bin = (int)(u >> 4);
                if (bin >= tb) {
                    int idx = i * 8 + q * 2 + h;
                    if (bin > tb) {
                        int p = atomicAdd(&n_sel, 1);
                        out[p] = idx;
                    } else {
                        int p = atomicAdd(&n_cand, 1);
                        if (p < 4096) { cand_u[p] = u; cand_i[p] = idx; }
                    }
                }
            }
        }
    }
    __syncthreads();

    const int need = NCAND - hi;
    const int C = min(n_cand, 4096);
    for (int i = tid; i < C; i += 256) {
        unsigned ui = cand_u[i];
        int ii = cand_i[i];
        int rank = 0;
        for (int j = 0; j < C; j++) {
            unsigned uj = cand_u[j];
            rank += (uj > ui) || (uj == ui && cand_i[j] < ii);
        }
        if (rank < need) out[hi + rank] = ii;
    }
}

// ------------------------- scheme-exact refine -------------------------------
__global__ void __launch_bounds__(128) refine_kernel(
    const float* __restrict__ X,
    const float* __restrict__ W,
    const float* __restrict__ bias,
    float* __restrict__ o_acts,
    float* __restrict__ o_idx) {
    __shared__ float xs[D_IN];
    __shared__ float vv[NCAND];
    __shared__ int   ci[NCAND];
    __shared__ int   si[KSEL];
    __shared__ float sv[KSEL];

    const int b   = blockIdx.x;
    const int tid = threadIdx.x;

    for (int i = tid; i < D_IN / 4; i += 128)
        ((float4*)xs)[i] = ((const float4*)(X + (size_t)b * D_IN))[i];
    if (tid < NCAND) ci[tid] = g_cidx[(size_t)b * NCAND + tid];
    __syncthreads();

    if (tid < 2 * NCAND) {
        const int cand = tid >> 1;
        const int half = tid & 1;
        const int l    = ci[cand];
        const float4* wr4 = (const float4*)(W + (size_t)l * D_IN + half * 512);
        const float4* xs4 = (const float4*)(xs + half * 512);
        float p = 0.f;
#pragma unroll 8
        for (int i = 0; i < 128; i++) {
            float4 w = wr4[i];
            float4 x = xs4[i];
            p = fmaf(x.x, w.x, p);
            p = fmaf(x.y, w.y, p);
            p = fmaf(x.z, w.z, p);
            p = fmaf(x.w, w.w, p);
        }
        float other = __shfl_xor_sync(0xFFFFFFFFu, p, 1);
        if (half == 0)
            vv[cand] = (p + other) + bias[l];
    }
    __syncthreads();

    if (tid < NCAND) {
        float vi = vv[tid];
        int   ii = ci[tid];
        int rank = 0;
#pragma unroll
        for (int j = 0; j < NCAND; j++) {
            float vj = vv[j];
            rank += (vj > vi) || (vj == vi && ci[j] < ii);
        }
        if (rank < KSEL) { si[rank] = ii; sv[rank] = vi; }
    }
    __syncthreads();

    if (tid < KSEL) {
        g_sidx[b * KSEL + tid] = si[tid];
        g_val [b * KSEL + tid] = fmaxf(sv[tid], 0.0f);
        if (o_idx) o_idx[(size_t)b * KSEL + tid] = (float)si[tid];
        if (o_acts)
            o_acts[(size_t)b * N_LAT + si[tid]] = fmaxf(sv[tid], 0.0f);
    }
}

// ------------------------- dec_w transpose ----------------------------------
__global__ void transp_kernel(const float* __restrict__ W, float* __restrict__ WT) {
    __shared__ float t[32][33];
    int l0 = blockIdx.x * 32;
    int d0 = blockIdx.y * 32;
    int txx = threadIdx.x, tyy = threadIdx.y;
#pragma unroll
    for (int j = 0; j < 32; j += 8)
        t[tyy + j][txx] = W[(size_t)(d0 + tyy + j) * N_LAT + l0 + txx];
    __syncthreads();
#pragma unroll
    for (int j = 0; j < 32; j += 8)
        WT[(size_t)(l0 + tyy + j) * D_IN + d0 + txx] = t[txx][tyy + j];
}

// ------------------------- sparse decode (512-latent panels) -----------------
__global__ void __launch_bounds__(256) decode_kernel(
    const float* __restrict__ WT,
    const float* __restrict__ dec_b,
    float* __restrict__ recon) {
    const int b   = blockIdx.x;
    const int tid = threadIdx.x;
    __shared__ float sv[KSEL];
    __shared__ int   sidx[KSEL];
    __shared__ float sv_s[KSEL];
    __shared__ int   sidx_s[KSEL];

    if (tid < KSEL) {
        sv[tid]   = g_val [b * KSEL + tid];
        sidx[tid] = g_sidx[b * KSEL + tid];
    }
    __syncthreads();
    if (tid < KSEL) {
        int ii = sidx[tid];
        int rank = 0;
#pragma unroll
        for (int j = 0; j < KSEL; j++) rank += (sidx[j] < ii);
        sidx_s[rank] = ii;
        sv_s[rank]   = sv[tid];
    }
    __syncthreads();

    const int d = tid * 4;
    float4 tot  = make_float4(0.f, 0.f, 0.f, 0.f);
    float4 pacc = make_float4(0.f, 0.f, 0.f, 0.f);
    int curPan = sidx_s[0] >> 9;
#pragma unroll
    for (int j = 0; j < KSEL; j++) {
        int   l = sidx_s[j];
        float v = sv_s[j];
        int pan = l >> 9;
        if (pan != curPan) {
            tot.x += pacc.x; tot.y += pacc.y; tot.z += pacc.z; tot.w += pacc.w;
            pacc = make_float4(0.f, 0.f, 0.f, 0.f);
            curPan = pan;
        }
        const float4 w = *(const float4*)&WT[(size_t)l * D_IN + d];
        pacc.x = fmaf(v, w.x, pacc.x);
        pacc.y = fmaf(v, w.y, pacc.y);
        pacc.z = fmaf(v, w.z, pacc.z);
        pacc.w = fmaf(v, w.w, pacc.w);
    }
    tot.x += pacc.x; tot.y += pacc.y; tot.z += pacc.z; tot.w += pacc.w;

    const float4 bb = *(const float4*)&dec_b[d];
    tot.x += bb.x; tot.y += bb.y; tot.z += bb.z; tot.w += bb.w;
    *(float4*)&recon[(size_t)b * D_IN + d] = tot;
}

// ------------------------- launch -------------------------------------------
extern "C" void kernel_launch(void* const* d_in, const int* in_sizes, int n_in,
                              void* d_out, int out_size) {
    const float* x     = (const float*)d_in[0];
    const float* enc_w = (const float*)d_in[1];
    const float* enc_b = (const float*)d_in[2];
    const float* dec_w = (const float*)d_in[3];
    const float* dec_b = (const float*)d_in[4];

    const size_t R = (size_t)B_ROWS * D_IN;
    const size_t A = (size_t)B_ROWS * N_LAT;
    const size_t I = (size_t)B_ROWS * KSEL;
    const size_t os = (size_t)out_size;

    float* out = (float*)d_out;
    float* o_recon = nullptr;
    float* o_acts  = nullptr;
    float* o_idx   = nullptr;
    if (os == R + A + I)      { o_recon = out; o_acts = out + R; o_idx = out + R + A; }
    else if (os == R + A)     { o_recon = out; o_acts = out + R; }
    else if (os == R + I)     { o_recon = out; o_idx  = out + R; }
    else if (os == A + I)     { o_acts  = out; o_idx  = out + A; }
    else if (os == R)         { o_recon = out; }
    else if (os == A)         { o_acts  = out; }
    else {
        o_recon = out;
        if (os >= R + A) o_acts = out + R;
        if (os >= R + A + I) o_idx = out + R + A;
    }

    __nv_bfloat16 *preb, *xb, *wb;
    float* wt;
    cudaGetSymbolAddress((void**)&preb, g_preb);
    cudaGetSymbolAddress((void**)&xb,   g_xb);
    cudaGetSymbolAddress((void**)&wb,   g_wb);
    cudaGetSymbolAddress((void**)&wt,   g_wt);

    // 1. convert x, enc_w to bf16
    cvt_bf16<<<(int)(R / 4 + 255) / 256, 256>>>(x, xb, (int)(R / 4));
    cvt_bf16<<<(int)(N_LAT * (size_t)D_IN / 4 + 255) / 256, 256>>>(
        enc_w, wb, (int)(N_LAT * (size_t)D_IN / 4));

    // 2. transpose dec_w (moved before GEMM: ncu capture slot -> GEMM)
    dim3 tgrid(N_LAT / 32, D_IN / 32);
    transp_kernel<<<tgrid, dim3(32, 8)>>>(dec_w, wt);

    // 3. bf16 mma.sync encoder GEMM (membership only) + acts zeroing
    cudaFuncSetAttribute(enc_gemm_bf16,
                         cudaFuncAttributeMaxDynamicSharedMemorySize, GSMEM);
    dim3 ggrid(N_LAT / 256, B_ROWS / 128);   // (64, 32)
    enc_gemm_bf16<<<ggrid, 512, GSMEM>>>(xb, wb, enc_b, preb, o_acts);

    // 4. top-NCAND candidate selection
    topk_kernel<<<B_ROWS, 256>>>(preb);

    // 5. scheme-exact refine: ordering, acts scatter, idx
    refine_kernel<<<B_ROWS, 128>>>(x, enc_w, enc_b, o_acts, o_idx);

    // 6. sparse decode (512-latent panels)
    if (o_recon)
        decode_kernel<<<B_ROWS, 256>>>(wt, dec_b, o_recon);
}

// round 15
// speedup vs baseline: 1.2939x; 1.0655x over previous
#include <cuda_runtime.h>
#include <cuda_bf16.h>
#include <cstdint>

// ---------------------------------------------------------------------------
// TopK SAE: B=4096, D_IN=1024, N_LAT=16384, K=32
// Outputs: [recon f32 | acts f32 | idx f32]
//
// Bit-exactness model (validated R6-R13, rel_err == 0.0):
//   enc pre_act = ((p0 + p1) + bias), p0 = serial FMA k=0..511, p1 = 512..1023
//   decode      = latent panels of 512 (l>>9), serial ascending-l FMA within
//                 panel, partials added ascending, + dec_b last
// Speed: bf16 mma.sync GEMM (membership-only) selects top-48 candidates;
// refine recomputes them scheme-exactly.
// R14: GEMM ncu showed 1 CTA/SM, tensor 42.6%, latency-bound. This round:
// 128x128 tiles / 256 threads (2 CTAs co-resident per SM) + 3-stage cp.async
// pipeline with ONE __syncthreads per k-iter.
// ---------------------------------------------------------------------------

#define B_ROWS   4096
#define D_IN     1024
#define N_LAT    16384
#define KSEL     32
#define NCAND    48

// ------------------------- device scratch ----------------------------------
__device__ __nv_bfloat16 g_preb[(size_t)B_ROWS * N_LAT];   // 128 MB
__device__ __nv_bfloat16 g_xb [(size_t)B_ROWS * D_IN];     // 8 MB
__device__ __nv_bfloat16 g_wb [(size_t)N_LAT * D_IN];      // 32 MB
__device__ float g_wt  [(size_t)N_LAT * D_IN];             // 64 MB (dec_w^T)
__device__ float g_val [B_ROWS * KSEL];
__device__ int   g_sidx[B_ROWS * KSEL];
__device__ int   g_cidx[B_ROWS * NCAND];

// ------------------------- mma / ldmatrix / cp.async helpers ----------------
__device__ __forceinline__ void ldsm4(uint32_t& r0, uint32_t& r1,
                                      uint32_t& r2, uint32_t& r3,
                                      uint32_t addr) {
    asm volatile("ldmatrix.sync.aligned.m8n8.x4.shared.b16 {%0,%1,%2,%3}, [%4];"
                 : "=r"(r0), "=r"(r1), "=r"(r2), "=r"(r3) : "r"(addr));
}
__device__ __forceinline__ void mma_bf16(float* c, const uint32_t* a,
                                         const uint32_t* b) {
    asm volatile(
        "mma.sync.aligned.m16n8k16.row.col.f32.bf16.bf16.f32 "
        "{%0,%1,%2,%3}, {%4,%5,%6,%7}, {%8,%9}, {%0,%1,%2,%3};"
        : "+f"(c[0]), "+f"(c[1]), "+f"(c[2]), "+f"(c[3])
        : "r"(a[0]), "r"(a[1]), "r"(a[2]), "r"(a[3]), "r"(b[0]), "r"(b[1]));
}
__device__ __forceinline__ void cp16(uint32_t dst, const void* src) {
    asm volatile("cp.async.cg.shared.global [%0], [%1], 16;"
                 :: "r"(dst), "l"(src));
}
#define CP_COMMIT()  asm volatile("cp.async.commit_group;" ::: "memory")
#define CP_WAIT(n)   asm volatile("cp.async.wait_group %0;" :: "n"(n) : "memory")

// ------------------------- fp32 -> bf16 conversion --------------------------
__global__ void __launch_bounds__(256) cvt_bf16(const float* __restrict__ src,
                                                __nv_bfloat16* __restrict__ dst,
                                                int n4) {
    int i = blockIdx.x * 256 + threadIdx.x;
    if (i < n4) {
        float4 v = ((const float4*)src)[i];
        __nv_bfloat162 lo = __floats2bfloat162_rn(v.x, v.y);
        __nv_bfloat162 hi = __floats2bfloat162_rn(v.z, v.w);
        uint2 pk;
        pk.x = *(uint32_t*)&lo;
        pk.y = *(uint32_t*)&hi;
        ((uint2*)dst)[i] = pk;
    }
}

// ------------------------- bf16 mma.sync encoder GEMM -----------------------
// P[4096,16384](bf16) = Xb * Wb^T + bias.  Also zeroes this CTA's 128x128
// region of acts (hidden behind tensor work).
// Tile 128(M) x 128(N) x 32(K), 256 threads (8 warps, 2m x 4n), warp tile
// 64x32 (4x4 m16n8k16). 3-stage cp.async pipeline, one sync per k-iter.
// 2 CTAs co-resident per SM (regs ~104 -> 53K; smem 60KB*2 -> 120KB).
constexpr int LDT = 40;                        // padded smem row (bf16 elems)
constexpr int ROW_B = 80;                      // row pitch bytes
constexpr int STAGE_BYTES = 256 * ROW_B;       // A(128 rows) + B(128 rows)
constexpr int B_OFF = 128 * ROW_B;             // B offset within a stage
constexpr int GSMEM = 3 * STAGE_BYTES;         // 61440

__global__ void __launch_bounds__(256) enc_gemm_bf16(
    const __nv_bfloat16* __restrict__ Xb,
    const __nv_bfloat16* __restrict__ Wb,
    const float* __restrict__ bias,
    __nv_bfloat16* __restrict__ P,
    float* __restrict__ acts) {
    extern __shared__ char smem[];

    const int tid    = threadIdx.x;
    const int wid    = tid >> 5;
    const int lane   = tid & 31;
    const int bm     = blockIdx.y * 128;
    const int bn     = blockIdx.x * 128;
    const int warp_m = (wid >> 2) * 64;     // 2 m-groups
    const int warp_n = (wid & 3) * 32;      // 4 n-groups

    float c[4][4][4];
#pragma unroll
    for (int i = 0; i < 4; i++)
#pragma unroll
        for (int j = 0; j < 4; j++)
#pragma unroll
            for (int q = 0; q < 4; q++) c[i][j][q] = 0.f;

    // loads: A = 512 x 16B segs, B = 512 x 16B segs; 2+2 per thread
    auto load_chunk = [&](int kt, int slot) {
        char* st = smem + slot * STAGE_BYTES;
#pragma unroll
        for (int r = 0; r < 2; r++) {
            int s   = tid + r * 256;
            int row = s >> 2;
            int sg  = s & 3;
            cp16((uint32_t)__cvta_generic_to_shared(st + row * ROW_B + sg * 16),
                 &Xb[(size_t)(bm + row) * D_IN + kt + sg * 8]);
            cp16((uint32_t)__cvta_generic_to_shared(st + B_OFF + row * ROW_B + sg * 16),
                 &Wb[(size_t)(bn + row) * D_IN + kt + sg * 8]);
        }
        CP_COMMIT();
    };

    load_chunk(0, 0);
    load_chunk(32, 1);

    // acts zeroing for this CTA's 128x128 region (overlaps with pipeline)
    if (acts) {
        const float4 z = make_float4(0.f, 0.f, 0.f, 0.f);
#pragma unroll
        for (int i = 0; i < 16; i++) {
            int idx = i * 256 + tid;          // 4096 float4 total
            int r   = idx >> 5;               // 0..127
            int c4  = idx & 31;               // 0..31
            *(float4*)&acts[(size_t)(bm + r) * N_LAT + bn + c4 * 4] = z;
        }
    }

    const int NT = D_IN / 32;   // 32
    for (int t = 0; t < NT; t++) {
        const int slot = t % 3;
        if (t == NT - 1) { CP_WAIT(0); } else { CP_WAIT(1); }
        __syncthreads();        // stage `slot` visible to all; prev stage free
        if (t + 2 < NT) load_chunk((t + 2) * 32, (t + 2) % 3);

        const __nv_bfloat16* Ab = (const __nv_bfloat16*)(smem + slot * STAGE_BYTES);
        const __nv_bfloat16* Bb = (const __nv_bfloat16*)(smem + slot * STAGE_BYTES + B_OFF);
#pragma unroll
        for (int s = 0; s < 2; s++) {              // two k16 halves
            uint32_t af[4][4];
#pragma unroll
            for (int mt = 0; mt < 4; mt++) {
                uint32_t addr = (uint32_t)__cvta_generic_to_shared(
                    Ab + (warp_m + mt * 16 + (lane & 15)) * LDT +
                    s * 16 + (lane >> 4) * 8);
                ldsm4(af[mt][0], af[mt][1], af[mt][2], af[mt][3], addr);
            }
            uint32_t bf[4][2];
#pragma unroll
            for (int p = 0; p < 2; p++) {
                uint32_t r0, r1, r2, r3;
                uint32_t addr = (uint32_t)__cvta_generic_to_shared(
                    Bb + (warp_n + p * 16 + (lane & 7) + ((lane >> 4) << 3)) * LDT +
                    s * 16 + (((lane >> 3) & 1) * 8));
                ldsm4(r0, r1, r2, r3, addr);
                bf[2 * p][0] = r0; bf[2 * p][1] = r1;
                bf[2 * p + 1][0] = r2; bf[2 * p + 1][1] = r3;
            }
#pragma unroll
            for (int mt = 0; mt < 4; mt++)
#pragma unroll
                for (int nt = 0; nt < 4; nt++)
                    mma_bf16(c[mt][nt], af[mt], bf[nt]);
        }
    }

    // epilogue: +bias, convert to bf16, store
#pragma unroll
    for (int nt = 0; nt < 4; nt++) {
        int col = bn + warp_n + nt * 8 + (lane & 3) * 2;
        float b0 = bias[col], b1 = bias[col + 1];
#pragma unroll
        for (int mt = 0; mt < 4; mt++) {
            int row0 = bm + warp_m + mt * 16 + (lane >> 2);
            __nv_bfloat162 v0 =
                __floats2bfloat162_rn(c[mt][nt][0] + b0, c[mt][nt][1] + b1);
            __nv_bfloat162 v1 =
                __floats2bfloat162_rn(c[mt][nt][2] + b0, c[mt][nt][3] + b1);
            *(__nv_bfloat162*)&P[(size_t)row0 * N_LAT + col] = v0;
            *(__nv_bfloat162*)&P[(size_t)(row0 + 8) * N_LAT + col] = v1;
        }
    }
}

// ------------------------- top-NCAND selection (bf16 pre) --------------------
__device__ __forceinline__ unsigned key16(unsigned short h) {
    return h ^ ((h & 0x8000u) ? 0xFFFFu : 0x8000u);
}

__global__ void __launch_bounds__(256) topk_kernel(
    const __nv_bfloat16* __restrict__ P) {
    __shared__ unsigned hist[4096];
    __shared__ int      cand_i[4096];
    __shared__ unsigned csum[256];
    __shared__ int      thr_bin, cnt_gt;
    __shared__ int      n_sel, n_cand;

    const int tid = threadIdx.x;
    const int b   = blockIdx.x;
    const unsigned short* row = (const unsigned short*)(P + (size_t)b * N_LAT);
    int* out = g_cidx + (size_t)b * NCAND;

    for (int i = tid; i < 4096; i += 256) hist[i] = 0;
    if (tid == 0) { n_sel = 0; n_cand = 0; }
    __syncthreads();

    const uint4* row8 = (const uint4*)row;
    for (int i = tid; i < N_LAT / 8; i += 256) {
        uint4 v = row8[i];
        unsigned w[4] = {v.x, v.y, v.z, v.w};
#pragma unroll
        for (int q = 0; q < 4; q++) {
            atomicAdd(&hist[key16((unsigned short)(w[q] & 0xFFFF)) >> 4], 1u);
            atomicAdd(&hist[key16((unsigned short)(w[q] >> 16)) >> 4], 1u);
        }
    }
    __syncthreads();

    {
        unsigned s = 0;
#pragma unroll 4
        for (int j = 0; j < 16; j++) s += hist[tid * 16 + j];
        csum[tid] = s;
    }
    __syncthreads();

    if (tid == 0) {
        unsigned acc = 0;
        int cchunk = 255;
        for (; cchunk >= 0; cchunk--) {
            if (acc + csum[cchunk] >= NCAND) break;
            acc += csum[cchunk];
        }
        int bin = cchunk * 16 + 15;
        for (; bin >= cchunk * 16; bin--) {
            if (acc + hist[bin] >= NCAND) break;
            acc += hist[bin];
        }
        thr_bin = bin;
        cnt_gt  = (int)acc;
    }
    __syncthreads();
    const int tb = thr_bin;
    const int hi = cnt_gt;
    __syncthreads();

    // pass 2 (vectorized): definite winners + threshold-bin candidates.
    unsigned* cand_u = hist;
    for (int i = tid; i < N_LAT / 8; i += 256) {
        uint4 v = row8[i];
        unsigned w[4] = {v.x, v.y, v.z, v.w};
#pragma unroll
        for (int q = 0; q < 4; q++) {
#pragma unroll
            for (int h = 0; h < 2; h++) {
                unsigned u = key16((unsigned short)((w[q] >> (16 * h)) & 0xFFFF));
                int bin = (int)(u >> 4);
                if (bin >= tb) {
                    int idx = i * 8 + q * 2 + h;
                    if (bin > tb) {
                        int p = atomicAdd(&n_sel, 1);
                        out[p] = idx;
                    } else {
                        int p = atomicAdd(&n_cand, 1);
                        if (p < 4096) { cand_u[p] = u; cand_i[p] = idx; }
                    }
                }
            }
        }
    }
    __syncthreads();

    const int need = NCAND - hi;
    const int C = min(n_cand, 4096);
    for (int i = tid; i < C; i += 256) {
        unsigned ui = cand_u[i];
        int ii = cand_i[i];
        int rank = 0;
        for (int j = 0; j < C; j++) {
            unsigned uj = cand_u[j];
            rank += (uj > ui) || (uj == ui && cand_i[j] < ii);
        }
        if (rank < need) out[hi + rank] = ii;
    }
}

// ------------------------- scheme-exact refine -------------------------------
__global__ void __launch_bounds__(128) refine_kernel(
    const float* __restrict__ X,
    const float* __restrict__ W,
    const float* __restrict__ bias,
    float* __restrict__ o_acts,
    float* __restrict__ o_idx) {
    __shared__ float xs[D_IN];
    __shared__ float vv[NCAND];
    __shared__ int   ci[NCAND];
    __shared__ int   si[KSEL];
    __shared__ float sv[KSEL];

    const int b   = blockIdx.x;
    const int tid = threadIdx.x;

    for (int i = tid; i < D_IN / 4; i += 128)
        ((float4*)xs)[i] = ((const float4*)(X + (size_t)b * D_IN))[i];
    if (tid < NCAND) ci[tid] = g_cidx[(size_t)b * NCAND + tid];
    __syncthreads();

    if (tid < 2 * NCAND) {
        const int cand = tid >> 1;
        const int half = tid & 1;
        const int l    = ci[cand];
        const float4* wr4 = (const float4*)(W + (size_t)l * D_IN + half * 512);
        const float4* xs4 = (const float4*)(xs + half * 512);
        float p = 0.f;
#pragma unroll 8
        for (int i = 0; i < 128; i++) {
            float4 w = wr4[i];
            float4 x = xs4[i];
            p = fmaf(x.x, w.x, p);
            p = fmaf(x.y, w.y, p);
            p = fmaf(x.z, w.z, p);
            p = fmaf(x.w, w.w, p);
        }
        float other = __shfl_xor_sync(0xFFFFFFFFu, p, 1);
        if (half == 0)
            vv[cand] = (p + other) + bias[l];
    }
    __syncthreads();

    if (tid < NCAND) {
        float vi = vv[tid];
        int   ii = ci[tid];
        int rank = 0;
#pragma unroll
        for (int j = 0; j < NCAND; j++) {
            float vj = vv[j];
            rank += (vj > vi) || (vj == vi && ci[j] < ii);
        }
        if (rank < KSEL) { si[rank] = ii; sv[rank] = vi; }
    }
    __syncthreads();

    if (tid < KSEL) {
        g_sidx[b * KSEL + tid] = si[tid];
        g_val [b * KSEL + tid] = fmaxf(sv[tid], 0.0f);
        if (o_idx) o_idx[(size_t)b * KSEL + tid] = (float)si[tid];
        if (o_acts)
            o_acts[(size_t)b * N_LAT + si[tid]] = fmaxf(sv[tid], 0.0f);
    }
}

// ------------------------- dec_w transpose ----------------------------------
__global__ void transp_kernel(const float* __restrict__ W, float* __restrict__ WT) {
    __shared__ float t[32][33];
    int l0 = blockIdx.x * 32;
    int d0 = blockIdx.y * 32;
    int txx = threadIdx.x, tyy = threadIdx.y;
#pragma unroll
    for (int j = 0; j < 32; j += 8)
        t[tyy + j][txx] = W[(size_t)(d0 + tyy + j) * N_LAT + l0 + txx];
    __syncthreads();
#pragma unroll
    for (int j = 0; j < 32; j += 8)
        WT[(size_t)(l0 + tyy + j) * D_IN + d0 + txx] = t[txx][tyy + j];
}

// ------------------------- sparse decode (512-latent panels) -----------------
__global__ void __launch_bounds__(256) decode_kernel(
    const float* __restrict__ WT,
    const float* __restrict__ dec_b,
    float* __restrict__ recon) {
    const int b   = blockIdx.x;
    const int tid = threadIdx.x;
    __shared__ float sv[KSEL];
    __shared__ int   sidx[KSEL];
    __shared__ float sv_s[KSEL];
    __shared__ int   sidx_s[KSEL];

    if (tid < KSEL) {
        sv[tid]   = g_val [b * KSEL + tid];
        sidx[tid] = g_sidx[b * KSEL + tid];
    }
    __syncthreads();
    if (tid < KSEL) {
        int ii = sidx[tid];
        int rank = 0;
#pragma unroll
        for (int j = 0; j < KSEL; j++) rank += (sidx[j] < ii);
        sidx_s[rank] = ii;
        sv_s[rank]   = sv[tid];
    }
    __syncthreads();

    const int d = tid * 4;
    float4 tot  = make_float4(0.f, 0.f, 0.f, 0.f);
    float4 pacc = make_float4(0.f, 0.f, 0.f, 0.f);
    int curPan = sidx_s[0] >> 9;
#pragma unroll
    for (int j = 0; j < KSEL; j++) {
        int   l = sidx_s[j];
        float v = sv_s[j];
        int pan = l >> 9;
        if (pan != curPan) {
            tot.x += pacc.x; tot.y += pacc.y; tot.z += pacc.z; tot.w += pacc.w;
            pacc = make_float4(0.f, 0.f, 0.f, 0.f);
            curPan = pan;
        }
        const float4 w = *(const float4*)&WT[(size_t)l * D_IN + d];
        pacc.x = fmaf(v, w.x, pacc.x);
        pacc.y = fmaf(v, w.y, pacc.y);
        pacc.z = fmaf(v, w.z, pacc.z);
        pacc.w = fmaf(v, w.w, pacc.w);
    }
    tot.x += pacc.x; tot.y += pacc.y; tot.z += pacc.z; tot.w += pacc.w;

    const float4 bb = *(const float4*)&dec_b[d];
    tot.x += bb.x; tot.y += bb.y; tot.z += bb.z; tot.w += bb.w;
    *(float4*)&recon[(size_t)b * D_IN + d] = tot;
}

// ------------------------- launch -------------------------------------------
extern "C" void kernel_launch(void* const* d_in, const int* in_sizes, int n_in,
                              void* d_out, int out_size) {
    const float* x     = (const float*)d_in[0];
    const float* enc_w = (const float*)d_in[1];
    const float* enc_b = (const float*)d_in[2];
    const float* dec_w = (const float*)d_in[3];
    const float* dec_b = (const float*)d_in[4];

    const size_t R = (size_t)B_ROWS * D_IN;
    const size_t A = (size_t)B_ROWS * N_LAT;
    const size_t I = (size_t)B_ROWS * KSEL;
    const size_t os = (size_t)out_size;

    float* out = (float*)d_out;
    float* o_recon = nullptr;
    float* o_acts  = nullptr;
    float* o_idx   = nullptr;
    if (os == R + A + I)      { o_recon = out; o_acts = out + R; o_idx = out + R + A; }
    else if (os == R + A)     { o_recon = out; o_acts = out + R; }
    else if (os == R + I)     { o_recon = out; o_idx  = out + R; }
    else if (os == A + I)     { o_acts  = out; o_idx  = out + A; }
    else if (os == R)         { o_recon = out; }
    else if (os == A)         { o_acts  = out; }
    else {
        o_recon = out;
        if (os >= R + A) o_acts = out + R;
        if (os >= R + A + I) o_idx = out + R + A;
    }

    __nv_bfloat16 *preb, *xb, *wb;
    float* wt;
    cudaGetSymbolAddress((void**)&preb, g_preb);
    cudaGetSymbolAddress((void**)&xb,   g_xb);
    cudaGetSymbolAddress((void**)&wb,   g_wb);
    cudaGetSymbolAddress((void**)&wt,   g_wt);

    // 1. convert x, enc_w to bf16
    cvt_bf16<<<(int)(R / 4 + 255) / 256, 256>>>(x, xb, (int)(R / 4));
    cvt_bf16<<<(int)(N_LAT * (size_t)D_IN / 4 + 255) / 256, 256>>>(
        enc_w, wb, (int)(N_LAT * (size_t)D_IN / 4));

    // 2. transpose dec_w (before GEMM: ncu capture slot -> GEMM)
    dim3 tgrid(N_LAT / 32, D_IN / 32);
    transp_kernel<<<tgrid, dim3(32, 8)>>>(dec_w, wt);

    // 3. bf16 mma.sync encoder GEMM (membership only) + acts zeroing
    cudaFuncSetAttribute(enc_gemm_bf16,
                         cudaFuncAttributeMaxDynamicSharedMemorySize, GSMEM);
    dim3 ggrid(N_LAT / 128, B_ROWS / 128);   // (128, 32)
    enc_gemm_bf16<<<ggrid, 256, GSMEM>>>(xb, wb, enc_b, preb, o_acts);

    // 4. top-NCAND candidate selection
    topk_kernel<<<B_ROWS, 256>>>(preb);

    // 5. scheme-exact refine: ordering, acts scatter, idx
    refine_kernel<<<B_ROWS, 128>>>(x, enc_w, enc_b, o_acts, o_idx);

    // 6. sparse decode (512-latent panels)
    if (o_recon)
        decode_kernel<<<B_ROWS, 256>>>(wt, dec_b, o_recon);
}

// round 16
// speedup vs baseline: 1.3276x; 1.0261x over previous
#include <cuda_runtime.h>
#include <cuda_bf16.h>
#include <cstdint>

// ---------------------------------------------------------------------------
// TopK SAE: B=4096, D_IN=1024, N_LAT=16384, K=32
// Outputs: [recon f32 | acts f32 | idx f32]
//
// Bit-exactness model (validated R6-R14, rel_err == 0.0):
//   enc pre_act = ((p0 + p1) + bias), p0 = serial FMA k=0..511, p1 = 512..1023
//   decode      = latent panels of 512 (l>>9), serial ascending-l FMA within
//                 panel, partials added ascending, + dec_b last
// Speed: bf16 mma.sync GEMM (membership-only) selects top-48 candidates;
// refine recomputes them scheme-exactly.
// R15: GEMM occupancy push #2 — 128x64 tiles, warp tile 32x32 (32 accum
// regs), __launch_bounds__(256,3) -> 3 CTAs / 24 warps per SM (was 16).
// ---------------------------------------------------------------------------

#define B_ROWS   4096
#define D_IN     1024
#define N_LAT    16384
#define KSEL     32
#define NCAND    48

// ------------------------- device scratch ----------------------------------
__device__ __nv_bfloat16 g_preb[(size_t)B_ROWS * N_LAT];   // 128 MB
__device__ __nv_bfloat16 g_xb [(size_t)B_ROWS * D_IN];     // 8 MB
__device__ __nv_bfloat16 g_wb [(size_t)N_LAT * D_IN];      // 32 MB
__device__ float g_wt  [(size_t)N_LAT * D_IN];             // 64 MB (dec_w^T)
__device__ float g_val [B_ROWS * KSEL];
__device__ int   g_sidx[B_ROWS * KSEL];
__device__ int   g_cidx[B_ROWS * NCAND];

// ------------------------- mma / ldmatrix / cp.async helpers ----------------
__device__ __forceinline__ void ldsm4(uint32_t& r0, uint32_t& r1,
                                      uint32_t& r2, uint32_t& r3,
                                      uint32_t addr) {
    asm volatile("ldmatrix.sync.aligned.m8n8.x4.shared.b16 {%0,%1,%2,%3}, [%4];"
                 : "=r"(r0), "=r"(r1), "=r"(r2), "=r"(r3) : "r"(addr));
}
__device__ __forceinline__ void mma_bf16(float* c, const uint32_t* a,
                                         const uint32_t* b) {
    asm volatile(
        "mma.sync.aligned.m16n8k16.row.col.f32.bf16.bf16.f32 "
        "{%0,%1,%2,%3}, {%4,%5,%6,%7}, {%8,%9}, {%0,%1,%2,%3};"
        : "+f"(c[0]), "+f"(c[1]), "+f"(c[2]), "+f"(c[3])
        : "r"(a[0]), "r"(a[1]), "r"(a[2]), "r"(a[3]), "r"(b[0]), "r"(b[1]));
}
__device__ __forceinline__ void cp16(uint32_t dst, const void* src) {
    asm volatile("cp.async.cg.shared.global [%0], [%1], 16;"
                 :: "r"(dst), "l"(src));
}
#define CP_COMMIT()  asm volatile("cp.async.commit_group;" ::: "memory")
#define CP_WAIT(n)   asm volatile("cp.async.wait_group %0;" :: "n"(n) : "memory")

// ------------------------- fp32 -> bf16 conversion --------------------------
__global__ void __launch_bounds__(256) cvt_bf16(const float* __restrict__ src,
                                                __nv_bfloat16* __restrict__ dst,
                                                int n4) {
    int i = blockIdx.x * 256 + threadIdx.x;
    if (i < n4) {
        float4 v = ((const float4*)src)[i];
        __nv_bfloat162 lo = __floats2bfloat162_rn(v.x, v.y);
        __nv_bfloat162 hi = __floats2bfloat162_rn(v.z, v.w);
        uint2 pk;
        pk.x = *(uint32_t*)&lo;
        pk.y = *(uint32_t*)&hi;
        ((uint2*)dst)[i] = pk;
    }
}

// ------------------------- bf16 mma.sync encoder GEMM -----------------------
// P[4096,16384](bf16) = Xb * Wb^T + bias.  Also zeroes this CTA's 128x64
// region of acts (hidden behind tensor work).
// Tile 128(M) x 64(N) x 32(K), 256 threads (8 warps, 4m x 2n), warp tile
// 32x32 (2x4 m16n8k16, 32 accum regs). 3-stage cp.async pipeline, one sync
// per k-iter. __launch_bounds__(256,3): 3 CTAs / 24 warps per SM.
constexpr int LDT = 40;                        // padded smem row (bf16 elems)
constexpr int ROW_B = 80;                      // row pitch bytes
constexpr int STAGE_BYTES = 192 * ROW_B;       // A(128 rows) + B(64 rows)
constexpr int B_OFF = 128 * ROW_B;             // B offset within a stage
constexpr int GSMEM = 3 * STAGE_BYTES;         // 46080

__global__ void __launch_bounds__(256, 3) enc_gemm_bf16(
    const __nv_bfloat16* __restrict__ Xb,
    const __nv_bfloat16* __restrict__ Wb,
    const float* __restrict__ bias,
    __nv_bfloat16* __restrict__ P,
    float* __restrict__ acts) {
    extern __shared__ char smem[];

    const int tid    = threadIdx.x;
    const int wid    = tid >> 5;
    const int lane   = tid & 31;
    const int bm     = blockIdx.y * 128;
    const int bn     = blockIdx.x * 64;
    const int warp_m = (wid >> 1) * 32;     // 4 m-groups
    const int warp_n = (wid & 1) * 32;      // 2 n-groups

    float c[2][4][4];
#pragma unroll
    for (int i = 0; i < 2; i++)
#pragma unroll
        for (int j = 0; j < 4; j++)
#pragma unroll
            for (int q = 0; q < 4; q++) c[i][j][q] = 0.f;

    // loads: A = 512 x 16B segs, B = 256 x 16B segs; 3 per thread
    auto load_chunk = [&](int kt, int slot) {
        char* st = smem + slot * STAGE_BYTES;
#pragma unroll
        for (int r = 0; r < 3; r++) {
            int s = tid + r * 256;
            if (s < 512) {                     // A segment
                int row = s >> 2, sg = s & 3;
                cp16((uint32_t)__cvta_generic_to_shared(st + row * ROW_B + sg * 16),
                     &Xb[(size_t)(bm + row) * D_IN + kt + sg * 8]);
            } else {                           // B segment
                int t2 = s - 512;
                int row = t2 >> 2, sg = t2 & 3;
                cp16((uint32_t)__cvta_generic_to_shared(st + B_OFF + row * ROW_B + sg * 16),
                     &Wb[(size_t)(bn + row) * D_IN + kt + sg * 8]);
            }
        }
        CP_COMMIT();
    };

    load_chunk(0, 0);
    load_chunk(32, 1);

    // acts zeroing for this CTA's 128x64 region (overlaps with pipeline)
    if (acts) {
        const float4 z = make_float4(0.f, 0.f, 0.f, 0.f);
#pragma unroll
        for (int i = 0; i < 8; i++) {
            int idx = i * 256 + tid;          // 2048 float4 total
            int r   = idx >> 4;               // 0..127
            int c4  = idx & 15;               // 0..15
            *(float4*)&acts[(size_t)(bm + r) * N_LAT + bn + c4 * 4] = z;
        }
    }

    const int NT = D_IN / 32;   // 32
    for (int t = 0; t < NT; t++) {
        const int slot = t % 3;
        if (t == NT - 1) { CP_WAIT(0); } else { CP_WAIT(1); }
        __syncthreads();        // stage `slot` visible; prev stage free
        if (t + 2 < NT) load_chunk((t + 2) * 32, (t + 2) % 3);

        const __nv_bfloat16* Ab = (const __nv_bfloat16*)(smem + slot * STAGE_BYTES);
        const __nv_bfloat16* Bb = (const __nv_bfloat16*)(smem + slot * STAGE_BYTES + B_OFF);
#pragma unroll
        for (int s = 0; s < 2; s++) {              // two k16 halves
            uint32_t af[2][4];
#pragma unroll
            for (int mt = 0; mt < 2; mt++) {
                uint32_t addr = (uint32_t)__cvta_generic_to_shared(
                    Ab + (warp_m + mt * 16 + (lane & 15)) * LDT +
                    s * 16 + (lane >> 4) * 8);
                ldsm4(af[mt][0], af[mt][1], af[mt][2], af[mt][3], addr);
            }
            uint32_t bf[4][2];
#pragma unroll
            for (int p = 0; p < 2; p++) {
                uint32_t r0, r1, r2, r3;
                uint32_t addr = (uint32_t)__cvta_generic_to_shared(
                    Bb + (warp_n + p * 16 + (lane & 7) + ((lane >> 4) << 3)) * LDT +
                    s * 16 + (((lane >> 3) & 1) * 8));
                ldsm4(r0, r1, r2, r3, addr);
                bf[2 * p][0] = r0; bf[2 * p][1] = r1;
                bf[2 * p + 1][0] = r2; bf[2 * p + 1][1] = r3;
            }
#pragma unroll
            for (int mt = 0; mt < 2; mt++)
#pragma unroll
                for (int nt = 0; nt < 4; nt++)
                    mma_bf16(c[mt][nt], af[mt], bf[nt]);
        }
    }

    // epilogue: +bias, convert to bf16, store
#pragma unroll
    for (int nt = 0; nt < 4; nt++) {
        int col = bn + warp_n + nt * 8 + (lane & 3) * 2;
        float b0 = bias[col], b1 = bias[col + 1];
#pragma unroll
        for (int mt = 0; mt < 2; mt++) {
            int row0 = bm + warp_m + mt * 16 + (lane >> 2);
            __nv_bfloat162 v0 =
                __floats2bfloat162_rn(c[mt][nt][0] + b0, c[mt][nt][1] + b1);
            __nv_bfloat162 v1 =
                __floats2bfloat162_rn(c[mt][nt][2] + b0, c[mt][nt][3] + b1);
            *(__nv_bfloat162*)&P[(size_t)row0 * N_LAT + col] = v0;
            *(__nv_bfloat162*)&P[(size_t)(row0 + 8) * N_LAT + col] = v1;
        }
    }
}

// ------------------------- top-NCAND selection (bf16 pre) --------------------
__device__ __forceinline__ unsigned key16(unsigned short h) {
    return h ^ ((h & 0x8000u) ? 0xFFFFu : 0x8000u);
}

__global__ void __launch_bounds__(256) topk_kernel(
    const __nv_bfloat16* __restrict__ P) {
    __shared__ unsigned hist[4096];
    __shared__ int      cand_i[4096];
    __shared__ unsigned csum[256];
    __shared__ int      thr_bin, cnt_gt;
    __shared__ int      n_sel, n_cand;

    const int tid = threadIdx.x;
    const int b   = blockIdx.x;
    const unsigned short* row = (const unsigned short*)(P + (size_t)b * N_LAT);
    int* out = g_cidx + (size_t)b * NCAND;

    for (int i = tid; i < 4096; i += 256) hist[i] = 0;
    if (tid == 0) { n_sel = 0; n_cand = 0; }
    __syncthreads();

    const uint4* row8 = (const uint4*)row;
    for (int i = tid; i < N_LAT / 8; i += 256) {
        uint4 v = row8[i];
        unsigned w[4] = {v.x, v.y, v.z, v.w};
#pragma unroll
        for (int q = 0; q < 4; q++) {
            atomicAdd(&hist[key16((unsigned short)(w[q] & 0xFFFF)) >> 4], 1u);
            atomicAdd(&hist[key16((unsigned short)(w[q] >> 16)) >> 4], 1u);
        }
    }
    __syncthreads();

    {
        unsigned s = 0;
#pragma unroll 4
        for (int j = 0; j < 16; j++) s += hist[tid * 16 + j];
        csum[tid] = s;
    }
    __syncthreads();

    if (tid == 0) {
        unsigned acc = 0;
        int cchunk = 255;
        for (; cchunk >= 0; cchunk--) {
            if (acc + csum[cchunk] >= NCAND) break;
            acc += csum[cchunk];
        }
        int bin = cchunk * 16 + 15;
        for (; bin >= cchunk * 16; bin--) {
            if (acc + hist[bin] >= NCAND) break;
            acc += hist[bin];
        }
        thr_bin = bin;
        cnt_gt  = (int)acc;
    }
    __syncthreads();
    const int tb = thr_bin;
    const int hi = cnt_gt;
    __syncthreads();

    // pass 2 (vectorized): definite winners + threshold-bin candidates.
    unsigned* cand_u = hist;
    for (int i = tid; i < N_LAT / 8; i += 256) {
        uint4 v = row8[i];
        unsigned w[4] = {v.x, v.y, v.z, v.w};
#pragma unroll
        for (int q = 0; q < 4; q++) {
#pragma unroll
            for (int h = 0; h < 2; h++) {
                unsigned u = key16((unsigned short)((w[q] >> (16 * h)) & 0xFFFF));
                int bin = (int)(u >> 4);
                if (bin >= tb) {
                    int idx = i * 8 + q * 2 + h;
                    if (bin > tb) {
                        int p = atomicAdd(&n_sel, 1);
                        out[p] = idx;
                    } else {
                        int p = atomicAdd(&n_cand, 1);
                        if (p < 4096) { cand_u[p] = u; cand_i[p] = idx; }
                    }
                }
            }
        }
    }
    __syncthreads();

    const int need = NCAND - hi;
    const int C = min(n_cand, 4096);
    for (int i = tid; i < C; i += 256) {
        unsigned ui = cand_u[i];
        int ii = cand_i[i];
        int rank = 0;
        for (int j = 0; j < C; j++) {
            unsigned uj = cand_u[j];
            rank += (uj > ui) || (uj == ui && cand_i[j] < ii);
        }
        if (rank < need) out[hi + rank] = ii;
    }
}

// ------------------------- scheme-exact refine -------------------------------
__global__ void __launch_bounds__(128) refine_kernel(
    const float* __restrict__ X,
    const float* __restrict__ W,
    const float* __restrict__ bias,
    float* __restrict__ o_acts,
    float* __restrict__ o_idx) {
    __shared__ float xs[D_IN];
    __shared__ float vv[NCAND];
    __shared__ int   ci[NCAND];
    __shared__ int   si[KSEL];
    __shared__ float sv[KSEL];

    const int b   = blockIdx.x;
    const int tid = threadIdx.x;

    for (int i = tid; i < D_IN / 4; i += 128)
        ((float4*)xs)[i] = ((const float4*)(X + (size_t)b * D_IN))[i];
    if (tid < NCAND) ci[tid] = g_cidx[(size_t)b * NCAND + tid];
    __syncthreads();

    if (tid < 2 * NCAND) {
        const int cand = tid >> 1;
        const int half = tid & 1;
        const int l    = ci[cand];
        const float4* wr4 = (const float4*)(W + (size_t)l * D_IN + half * 512);
        const float4* xs4 = (const float4*)(xs + half * 512);
        float p = 0.f;
#pragma unroll 8
        for (int i = 0; i < 128; i++) {
            float4 w = wr4[i];
            float4 x = xs4[i];
            p = fmaf(x.x, w.x, p);
            p = fmaf(x.y, w.y, p);
            p = fmaf(x.z, w.z, p);
            p = fmaf(x.w, w.w, p);
        }
        float other = __shfl_xor_sync(0xFFFFFFFFu, p, 1);
        if (half == 0)
            vv[cand] = (p + other) + bias[l];
    }
    __syncthreads();

    if (tid < NCAND) {
        float vi = vv[tid];
        int   ii = ci[tid];
        int rank = 0;
#pragma unroll
        for (int j = 0; j < NCAND; j++) {
            float vj = vv[j];
            rank += (vj > vi) || (vj == vi && ci[j] < ii);
        }
        if (rank < KSEL) { si[rank] = ii; sv[rank] = vi; }
    }
    __syncthreads();

    if (tid < KSEL) {
        g_sidx[b * KSEL + tid] = si[tid];
        g_val [b * KSEL + tid] = fmaxf(sv[tid], 0.0f);
        if (o_idx) o_idx[(size_t)b * KSEL + tid] = (float)si[tid];
        if (o_acts)
            o_acts[(size_t)b * N_LAT + si[tid]] = fmaxf(sv[tid], 0.0f);
    }
}

// ------------------------- dec_w transpose ----------------------------------
__global__ void transp_kernel(const float* __restrict__ W, float* __restrict__ WT) {
    __shared__ float t[32][33];
    int l0 = blockIdx.x * 32;
    int d0 = blockIdx.y * 32;
    int txx = threadIdx.x, tyy = threadIdx.y;
#pragma unroll
    for (int j = 0; j < 32; j += 8)
        t[tyy + j][txx] = W[(size_t)(d0 + tyy + j) * N_LAT + l0 + txx];
    __syncthreads();
#pragma unroll
    for (int j = 0; j < 32; j += 8)
        WT[(size_t)(l0 + tyy + j) * D_IN + d0 + txx] = t[txx][tyy + j];
}

// ------------------------- sparse decode (512-latent panels) -----------------
__global__ void __launch_bounds__(256) decode_kernel(
    const float* __restrict__ WT,
    const float* __restrict__ dec_b,
    float* __restrict__ recon) {
    const int b   = blockIdx.x;
    const int tid = threadIdx.x;
    __shared__ float sv[KSEL];
    __shared__ int   sidx[KSEL];
    __shared__ float sv_s[KSEL];
    __shared__ int   sidx_s[KSEL];

    if (tid < KSEL) {
        sv[tid]   = g_val [b * KSEL + tid];
        sidx[tid] = g_sidx[b * KSEL + tid];
    }
    __syncthreads();
    if (tid < KSEL) {
        int ii = sidx[tid];
        int rank = 0;
#pragma unroll
        for (int j = 0; j < KSEL; j++) rank += (sidx[j] < ii);
        sidx_s[rank] = ii;
        sv_s[rank]   = sv[tid];
    }
    __syncthreads();

    const int d = tid * 4;
    float4 tot  = make_float4(0.f, 0.f, 0.f, 0.f);
    float4 pacc = make_float4(0.f, 0.f, 0.f, 0.f);
    int curPan = sidx_s[0] >> 9;
#pragma unroll
    for (int j = 0; j < KSEL; j++) {
        int   l = sidx_s[j];
        float v = sv_s[j];
        int pan = l >> 9;
        if (pan != curPan) {
            tot.x += pacc.x; tot.y += pacc.y; tot.z += pacc.z; tot.w += pacc.w;
            pacc = make_float4(0.f, 0.f, 0.f, 0.f);
            curPan = pan;
        }
        const float4 w = *(const float4*)&WT[(size_t)l * D_IN + d];
        pacc.x = fmaf(v, w.x, pacc.x);
        pacc.y = fmaf(v, w.y, pacc.y);
        pacc.z = fmaf(v, w.z, pacc.z);
        pacc.w = fmaf(v, w.w, pacc.w);
    }
    tot.x += pacc.x; tot.y += pacc.y; tot.z += pacc.z; tot.w += pacc.w;

    const float4 bb = *(const float4*)&dec_b[d];
    tot.x += bb.x; tot.y += bb.y; tot.z += bb.z; tot.w += bb.w;
    *(float4*)&recon[(size_t)b * D_IN + d] = tot;
}

// ------------------------- launch -------------------------------------------
extern "C" void kernel_launch(void* const* d_in, const int* in_sizes, int n_in,
                              void* d_out, int out_size) {
    const float* x     = (const float*)d_in[0];
    const float* enc_w = (const float*)d_in[1];
    const float* enc_b = (const float*)d_in[2];
    const float* dec_w = (const float*)d_in[3];
    const float* dec_b = (const float*)d_in[4];

    const size_t R = (size_t)B_ROWS * D_IN;
    const size_t A = (size_t)B_ROWS * N_LAT;
    const size_t I = (size_t)B_ROWS * KSEL;
    const size_t os = (size_t)out_size;

    float* out = (float*)d_out;
    float* o_recon = nullptr;
    float* o_acts  = nullptr;
    float* o_idx   = nullptr;
    if (os == R + A + I)      { o_recon = out; o_acts = out + R; o_idx = out + R + A; }
    else if (os == R + A)     { o_recon = out; o_acts = out + R; }
    else if (os == R + I)     { o_recon = out; o_idx  = out + R; }
    else if (os == A + I)     { o_acts  = out; o_idx  = out + A; }
    else if (os == R)         { o_recon = out; }
    else if (os == A)         { o_acts  = out; }
    else {
        o_recon = out;
        if (os >= R + A) o_acts = out + R;
        if (os >= R + A + I) o_idx = out + R + A;
    }

    __nv_bfloat16 *preb, *xb, *wb;
    float* wt;
    cudaGetSymbolAddress((void**)&preb, g_preb);
    cudaGetSymbolAddress((void**)&xb,   g_xb);
    cudaGetSymbolAddress((void**)&wb,   g_wb);
    cudaGetSymbolAddress((void**)&wt,   g_wt);

    // 1. convert x, enc_w to bf16
    cvt_bf16<<<(int)(R / 4 + 255) / 256, 256>>>(x, xb, (int)(R / 4));
    cvt_bf16<<<(int)(N_LAT * (size_t)D_IN / 4 + 255) / 256, 256>>>(
        enc_w, wb, (int)(N_LAT * (size_t)D_IN / 4));

    // 2. transpose dec_w (before GEMM: ncu capture slot -> GEMM)
    dim3 tgrid(N_LAT / 32, D_IN / 32);
    transp_kernel<<<tgrid, dim3(32, 8)>>>(dec_w, wt);

    // 3. bf16 mma.sync encoder GEMM (membership only) + acts zeroing
    cudaFuncSetAttribute(enc_gemm_bf16,
                         cudaFuncAttributeMaxDynamicSharedMemorySize, GSMEM);
    dim3 ggrid(N_LAT / 64, B_ROWS / 128);   // (256, 32)
    enc_gemm_bf16<<<ggrid, 256, GSMEM>>>(xb, wb, enc_b, preb, o_acts);

    // 4. top-NCAND candidate selection
    topk_kernel<<<B_ROWS, 256>>>(preb);

    // 5. scheme-exact refine: ordering, acts scatter, idx
    refine_kernel<<<B_ROWS, 128>>>(x, enc_w, enc_b, o_acts, o_idx);

    // 6. sparse decode (512-latent panels)
    if (o_recon)
        decode_kernel<<<B_ROWS, 256>>>(wt, dec_b, o_recon);
}